// round 5
// baseline (speedup 1.0000x reference)
#include <cuda_runtime.h>
#include <cuda_fp16.h>
#include <math.h>
#include <stdint.h>

#define S    8192
#define CC   512
#define NHW  1024
#define BM   128
#define BN   256
#define BK   64
#define NST  3
#define A_BYTES 16384                  // 128 rows x 128 B
#define B_BYTES 32768                  // 256 rows x 128 B
#define STG (A_BYTES + B_BYTES)        // 48 KB
#define SMT (NST * STG)                // 144 KB

// ---------------- scratch (__device__ globals) ----------------
__device__ float  g_f1[S * CC];
__device__ float  g_f2[S * CC];
__device__ float  g_sc[(size_t)S * S];       // fp32 scores
__device__ __half g_ha[S * CC];              // normed activations
__device__ __half g_ha2[S * CC];             // attn pre-proj
__device__ __half g_hq[S * CC];
__device__ __half g_hk[S * CC];
__device__ __half g_hv[S * CC];
__device__ __half g_hvt[CC * S];             // V^T
__device__ __half g_hp[(size_t)S * S];       // fp16 probabilities
__device__ __half g_hwt[CC * 27 * CC];       // transposed conv weight
__device__ __half g_hw1[CC * CC];            // transposed 1x1 weight

// ---------------- helpers ----------------
__device__ __forceinline__ uint32_t smem_u32(const void* p) {
    return (uint32_t)__cvta_generic_to_shared(p);
}
__device__ __forceinline__ void cp_async16(uint32_t smem, const void* gmem) {
    asm volatile("cp.async.cg.shared.global [%0], [%1], 16;\n" :: "r"(smem), "l"(gmem));
}
__device__ __forceinline__ void cp_commit() { asm volatile("cp.async.commit_group;\n"); }
__device__ __forceinline__ void cp_wait_n(int tail) {
    if (tail >= 2)      asm volatile("cp.async.wait_group 2;\n");
    else if (tail == 1) asm volatile("cp.async.wait_group 1;\n");
    else                asm volatile("cp.async.wait_group 0;\n");
}
#define SWZ(o) ((o) ^ (((o) >> 3) & 0x70))

__device__ __forceinline__ void ldm4(uint32_t* r, uint32_t addr) {
    asm volatile("ldmatrix.sync.aligned.m8n8.x4.shared.b16 {%0,%1,%2,%3}, [%4];\n"
                 : "=r"(r[0]), "=r"(r[1]), "=r"(r[2]), "=r"(r[3]) : "r"(addr));
}
__device__ __forceinline__ void mma16816(float* c, const uint32_t* a, uint32_t b0, uint32_t b1) {
    asm volatile(
        "mma.sync.aligned.m16n8k16.row.col.f32.f16.f16.f32 "
        "{%0,%1,%2,%3}, {%4,%5,%6,%7}, {%8,%9}, {%0,%1,%2,%3};\n"
        : "+f"(c[0]), "+f"(c[1]), "+f"(c[2]), "+f"(c[3])
        : "r"(a[0]), "r"(a[1]), "r"(a[2]), "r"(a[3]), "r"(b0), "r"(b1));
}

// ===========================================================================
// Unified fp16 mma.sync GEMM.  CTA 128x256, warp 64x64, BK=64, 3-stage.
// out[m,n] = scale * (sum_k A[src(m),k] * Bt[n,k]) (+bias) (+res)
// mode: 0 = linear, 1 = conv27, 2 = QK (block skip + fp32 out), 3 = PV (L-limited)
// ===========================================================================
__global__ __launch_bounds__(256, 1) void tc_gemm(
    const __half* __restrict__ A, int lda,
    const __half* __restrict__ Bt, int ldb,
    const float* __restrict__ bias, const float* __restrict__ res,
    void* __restrict__ outp, int ldo, int out_half,
    int nIterIn, int mode, float scale)
{
    extern __shared__ char smem[];
    int tid = threadIdx.x;
    int m0 = blockIdx.x * BM;
    int n0 = blockIdx.y * BN;

    if (mode == 2 && (n0 >> 10) > (m0 >> 10)) return;

    int nIter = nIterIn;
    if (mode == 3) nIter = ((m0 >> 10) + 1) * (NHW / BK);

    uint32_t sbase = smem_u32(smem);

    // A loader: 128 rows x 8 chunks = 1024 chunks, 4/thread
    int arow[4], acol[4]; uint32_t asw[4];
    int at[4], ay[4], ax[4];
#pragma unroll
    for (int j = 0; j < 4; ++j) {
        int ch = tid + j * 256;
        arow[j] = ch >> 3; acol[j] = ch & 7;
        asw[j] = SWZ(arow[j] * 128 + acol[j] * 16);
        int m = m0 + arow[j];
        at[j] = m >> 10; ay[j] = (m >> 5) & 31; ax[j] = m & 31;
    }
    // B loader: 256 rows x 8 chunks = 2048 chunks, 8/thread
    int brow[8], bcol[8]; uint32_t bsw[8];
#pragma unroll
    for (int j = 0; j < 8; ++j) {
        int ch = tid + j * 256;
        brow[j] = ch >> 3; bcol[j] = ch & 7;
        bsw[j] = SWZ(brow[j] * 128 + bcol[j] * 16);
    }

    auto load_stage = [&](int it, int buf) {
        uint32_t sA = sbase + buf * STG;
        uint32_t sB = sA + A_BYTES;
        int kcA, dt = 0, dy = 0, dx = 0;
        if (mode == 1) {
            int tap = it >> 3; kcA = (it & 7) << 6;
            dt = tap / 9 - 2; dy = (tap / 3) % 3 - 1; dx = tap % 3 - 1;
        } else kcA = it << 6;
        int kcB = it << 6;
#pragma unroll
        for (int j = 0; j < 4; ++j) {
            int src;
            if (mode == 1) {
                int st = at[j] + dt; st = st < 0 ? 0 : st;
                int sy = ay[j] + dy; sy = sy < 0 ? 0 : (sy > 31 ? 31 : sy);
                int sx = ax[j] + dx; sx = sx < 0 ? 0 : (sx > 31 ? 31 : sx);
                src = (st << 10) + (sy << 5) + sx;
            } else src = m0 + arow[j];
            cp_async16(sA + asw[j], A + (size_t)src * lda + kcA + acol[j] * 8);
        }
#pragma unroll
        for (int j = 0; j < 8; ++j)
            cp_async16(sB + bsw[j], Bt + (size_t)(n0 + brow[j]) * ldb + kcB + bcol[j] * 8);
        cp_commit();
    };

    int wid = tid >> 5, lane = tid & 31;
    int warpM = wid & 1, warpN = wid >> 1;        // 2 x 4 warps, warp tile 64x64
    int rA = (lane & 7) + ((lane >> 3) & 1) * 8;  // ldmatrix row-in-16
    int khalf = (lane >> 4) & 1;                  // +16B for k-hi

    float acc[4][8][4];
#pragma unroll
    for (int i = 0; i < 4; ++i)
#pragma unroll
        for (int j = 0; j < 8; ++j)
#pragma unroll
            for (int e = 0; e < 4; ++e) acc[i][j][e] = 0.f;

    for (int s = 0; s < NST && s < nIter; ++s) load_stage(s, s);

    for (int it = 0; it < nIter; ++it) {
        int buf = it % NST;
        cp_wait_n(nIter - 1 - it);
        __syncthreads();
        uint32_t sA = sbase + buf * STG;
        uint32_t sB = sA + A_BYTES;
#pragma unroll
        for (int kk = 0; kk < 4; ++kk) {
            uint32_t afr[4][4], bfr[4][4];
#pragma unroll
            for (int mi = 0; mi < 4; ++mi)
                ldm4(afr[mi], sA + SWZ((warpM * 64 + mi * 16 + rA) * 128 + kk * 32 + khalf * 16));
#pragma unroll
            for (int nj = 0; nj < 4; ++nj)
                ldm4(bfr[nj], sB + SWZ((warpN * 64 + nj * 16 + rA) * 128 + kk * 32 + khalf * 16));
#pragma unroll
            for (int mi = 0; mi < 4; ++mi)
#pragma unroll
                for (int nf = 0; nf < 8; ++nf) {
                    int nj = nf >> 1, h = nf & 1;
                    mma16816(acc[mi][nf], afr[mi], bfr[nj][h], bfr[nj][h + 2]);
                }
        }
        __syncthreads();
        if (it + NST < nIter) load_stage(it + NST, buf);
    }

    // epilogue
    int r0 = lane >> 2, c0 = (lane & 3) * 2;
#pragma unroll
    for (int mi = 0; mi < 4; ++mi)
#pragma unroll
        for (int nf = 0; nf < 8; ++nf) {
            int gm = m0 + warpM * 64 + mi * 16 + r0;
            int gn = n0 + warpN * 64 + nf * 8 + c0;
#pragma unroll
            for (int hrow = 0; hrow < 2; ++hrow) {
                int m = gm + hrow * 8;
                float vx = acc[mi][nf][hrow * 2 + 0] * scale;
                float vy = acc[mi][nf][hrow * 2 + 1] * scale;
                if (bias) { vx += bias[gn]; vy += bias[gn + 1]; }
                if (res) {
                    const float2 rr = *(const float2*)&res[(size_t)m * ldo + gn];
                    vx += rr.x; vy += rr.y;
                }
                if (out_half) {
                    __half2* o = (__half2*)((__half*)outp + (size_t)m * ldo + gn);
                    *o = __floats2half2_rn(vx, vy);
                } else {
                    float2* o = (float2*)((float*)outp + (size_t)m * ldo + gn);
                    *o = make_float2(vx, vy);
                }
            }
        }
}

// ---------------------------------------------------------------------------
// weight convert+transpose: src fp32 [R][Cn] -> dst fp16 [Cn][R]
// ---------------------------------------------------------------------------
__global__ __launch_bounds__(256) void wcvt(
    const float* __restrict__ src, __half* __restrict__ dst, int R, int Cn)
{
    __shared__ float t[32][33];
    int r0 = blockIdx.x * 32, c0 = blockIdx.y * 32;
    int x = threadIdx.x & 31, y = threadIdx.x >> 5;
#pragma unroll
    for (int i = 0; i < 4; ++i)
        t[y + i * 8][x] = src[(size_t)(r0 + y + i * 8) * Cn + c0 + x];
    __syncthreads();
#pragma unroll
    for (int i = 0; i < 4; ++i)
        dst[(size_t)(c0 + y + i * 8) * R + r0 + x] = __float2half_rn(t[x][y + i * 8]);
}

// half transpose: src [R][Cn] -> dst [Cn][R]
__global__ __launch_bounds__(256) void htrans(
    const __half* __restrict__ src, __half* __restrict__ dst, int R, int Cn)
{
    __shared__ __half t[32][34];
    int r0 = blockIdx.x * 32, c0 = blockIdx.y * 32;
    int x = threadIdx.x & 31, y = threadIdx.x >> 5;
#pragma unroll
    for (int i = 0; i < 4; ++i)
        t[y + i * 8][x] = src[(size_t)(r0 + y + i * 8) * Cn + c0 + x];
    __syncthreads();
#pragma unroll
    for (int i = 0; i < 4; ++i)
        dst[(size_t)(c0 + y + i * 8) * R + r0 + x] = t[x][y + i * 8];
}

// ---------------------------------------------------------------------------
// rmsnorm (+ optional silu): fp32 in, fp16 out
// ---------------------------------------------------------------------------
__global__ __launch_bounds__(256) void rmsnorm_kernel(
    const float* __restrict__ X, const float* __restrict__ g,
    __half* __restrict__ out, int dosilu)
{
    int m = blockIdx.x;
    const float* xr = X + (size_t)m * CC;
    __half* orow = out + (size_t)m * CC;
    int tid = threadIdx.x;
    float x0 = xr[tid], x1 = xr[tid + 256];
    __shared__ float red[256];
    red[tid] = x0 * x0 + x1 * x1;
    __syncthreads();
    for (int s = 128; s > 0; s >>= 1) {
        if (tid < s) red[tid] += red[tid + s];
        __syncthreads();
    }
    float scale = 22.627416997969522f / (sqrtf(red[0]) + 1e-8f);
    float y0 = x0 * scale * g[tid];
    float y1 = x1 * scale * g[tid + 256];
    if (dosilu) {
        y0 = y0 / (1.0f + __expf(-y0));
        y1 = y1 / (1.0f + __expf(-y1));
    }
    orow[tid] = __float2half_rn(y0);
    orow[tid + 256] = __float2half_rn(y1);
}

// ---------------------------------------------------------------------------
// softmax: fp32 scores -> fp16 probabilities, valid length L = (frame+1)*1024
// ---------------------------------------------------------------------------
__global__ __launch_bounds__(256) void softmax_kernel(
    const float* __restrict__ Sc, __half* __restrict__ P)
{
    int m = blockIdx.x;
    int L4 = ((m >> 10) + 1) << 8;   // L/4
    const float4* row = (const float4*)(Sc + (size_t)m * S);
    __half2* prow = (__half2*)(P + (size_t)m * S);
    int tid = threadIdx.x;
    __shared__ float rm[256], rs[256];

    float mx = -3.4e38f, sm = 0.f;
    for (int i = tid; i < L4; i += 256) {
        float4 v = row[i];
        float bm = fmaxf(fmaxf(v.x, v.y), fmaxf(v.z, v.w));
        if (bm > mx) { sm *= __expf(mx - bm); mx = bm; }
        sm += __expf(v.x - mx) + __expf(v.y - mx) + __expf(v.z - mx) + __expf(v.w - mx);
    }
    rm[tid] = mx; rs[tid] = sm;
    __syncthreads();
    for (int s = 128; s > 0; s >>= 1) {
        if (tid < s) {
            float m2 = rm[tid + s], s2 = rs[tid + s];
            float M = fmaxf(rm[tid], m2);
            rs[tid] = rs[tid] * __expf(rm[tid] - M) + s2 * __expf(m2 - M);
            rm[tid] = M;
        }
        __syncthreads();
    }
    float M = rm[0];
    float inv = 1.f / rs[0];

    for (int i = tid; i < L4; i += 256) {
        float4 v = row[i];
        float p0 = __expf(v.x - M) * inv, p1 = __expf(v.y - M) * inv;
        float p2 = __expf(v.z - M) * inv, p3 = __expf(v.w - M) * inv;
        prow[i * 2 + 0] = __floats2half2_rn(p0, p1);
        prow[i * 2 + 1] = __floats2half2_rn(p2, p3);
    }
}

// ---------------------------------------------------------------------------
extern "C" void kernel_launch(void* const* d_in, const int* in_sizes, int n_in,
                              void* d_out, int out_size)
{
    const float* x    = (const float*)d_in[0];
    const float* r1g1 = (const float*)d_in[1];
    const float* r1w1 = (const float*)d_in[2];
    const float* r1b1 = (const float*)d_in[3];
    const float* r1g2 = (const float*)d_in[4];
    const float* r1w2 = (const float*)d_in[5];
    const float* r1b2 = (const float*)d_in[6];
    const float* atg  = (const float*)d_in[7];
    const float* qw   = (const float*)d_in[8];
    const float* qb   = (const float*)d_in[9];
    const float* kw   = (const float*)d_in[10];
    const float* kb   = (const float*)d_in[11];
    const float* vw   = (const float*)d_in[12];
    const float* vb   = (const float*)d_in[13];
    const float* pw   = (const float*)d_in[14];
    const float* pb   = (const float*)d_in[15];
    const float* r2g1 = (const float*)d_in[16];
    const float* r2w1 = (const float*)d_in[17];
    const float* r2b1 = (const float*)d_in[18];
    const float* r2g2 = (const float*)d_in[19];
    const float* r2w2 = (const float*)d_in[20];
    const float* r2b2 = (const float*)d_in[21];
    float* out = (float*)d_out;

    float *f1, *f2, *sc;
    __half *ha, *ha2, *hq, *hk, *hv, *hvt, *hp, *hwt, *hw1;
    cudaGetSymbolAddress((void**)&f1,  g_f1);
    cudaGetSymbolAddress((void**)&f2,  g_f2);
    cudaGetSymbolAddress((void**)&sc,  g_sc);
    cudaGetSymbolAddress((void**)&ha,  g_ha);
    cudaGetSymbolAddress((void**)&ha2, g_ha2);
    cudaGetSymbolAddress((void**)&hq,  g_hq);
    cudaGetSymbolAddress((void**)&hk,  g_hk);
    cudaGetSymbolAddress((void**)&hv,  g_hv);
    cudaGetSymbolAddress((void**)&hvt, g_hvt);
    cudaGetSymbolAddress((void**)&hp,  g_hp);
    cudaGetSymbolAddress((void**)&hwt, g_hwt);
    cudaGetSymbolAddress((void**)&hw1, g_hw1);

    cudaFuncSetAttribute(tc_gemm, cudaFuncAttributeMaxDynamicSharedMemorySize, SMT);

    dim3 blk(256);
    dim3 gGrid(S / BM, CC / BN);      // 64 x 2
    dim3 qkGrid(S / BM, S / BN);      // 64 x 32
    dim3 wcGrid(27 * CC / 32, CC / 32);
    dim3 w1Grid(CC / 32, CC / 32);
    dim3 vtGrid(S / 32, CC / 32);
    const float qscale = 0.044194173824159216f;  // 1/sqrt(512)
    const int KC = 27 * CC;

    // ---- resnet 1 ----
    rmsnorm_kernel<<<S, blk>>>(x, r1g1, ha, 1);
    wcvt<<<wcGrid, blk>>>(r1w1, hwt, KC, CC);
    tc_gemm<<<gGrid, blk, SMT>>>(ha, CC, hwt, KC, r1b1, nullptr, f1, CC, 0, 27 * 8, 1, 1.f);
    rmsnorm_kernel<<<S, blk>>>(f1, r1g2, ha, 1);
    wcvt<<<wcGrid, blk>>>(r1w2, hwt, KC, CC);
    tc_gemm<<<gGrid, blk, SMT>>>(ha, CC, hwt, KC, r1b2, x, f1, CC, 0, 27 * 8, 1, 1.f);  // f1 = resnet1

    // ---- attention ----
    rmsnorm_kernel<<<S, blk>>>(f1, atg, ha, 0);
    wcvt<<<w1Grid, blk>>>(qw, hw1, CC, CC);
    tc_gemm<<<gGrid, blk, SMT>>>(ha, CC, hw1, CC, qb, nullptr, hq, CC, 1, 8, 0, 1.f);
    wcvt<<<w1Grid, blk>>>(kw, hw1, CC, CC);
    tc_gemm<<<gGrid, blk, SMT>>>(ha, CC, hw1, CC, kb, nullptr, hk, CC, 1, 8, 0, 1.f);
    wcvt<<<w1Grid, blk>>>(vw, hw1, CC, CC);
    tc_gemm<<<gGrid, blk, SMT>>>(ha, CC, hw1, CC, vb, nullptr, hv, CC, 1, 8, 0, 1.f);
    htrans<<<vtGrid, blk>>>(hv, hvt, S, CC);
    tc_gemm<<<qkGrid, blk, SMT>>>(hq, CC, hk, CC, nullptr, nullptr, sc, S, 0, 8, 2, qscale);
    softmax_kernel<<<S, blk>>>(sc, hp);
    tc_gemm<<<gGrid, blk, SMT>>>(hp, S, hvt, S, nullptr, nullptr, ha2, CC, 1, 0, 3, 1.f);
    wcvt<<<w1Grid, blk>>>(pw, hw1, CC, CC);
    tc_gemm<<<gGrid, blk, SMT>>>(ha2, CC, hw1, CC, pb, f1, f2, CC, 0, 8, 0, 1.f);        // f2 = attn out

    // ---- resnet 2 ----
    rmsnorm_kernel<<<S, blk>>>(f2, r2g1, ha, 1);
    wcvt<<<wcGrid, blk>>>(r2w1, hwt, KC, CC);
    tc_gemm<<<gGrid, blk, SMT>>>(ha, CC, hwt, KC, r2b1, nullptr, f1, CC, 0, 27 * 8, 1, 1.f);
    rmsnorm_kernel<<<S, blk>>>(f1, r2g2, ha, 1);
    wcvt<<<wcGrid, blk>>>(r2w2, hwt, KC, CC);
    tc_gemm<<<gGrid, blk, SMT>>>(ha, CC, hwt, KC, r2b2, f2, out, CC, 0, 27 * 8, 1, 1.f);
}